// round 16
// baseline (speedup 1.0000x reference)
#include <cuda_runtime.h>

#define NN 100000
#define EE 1600000
#define ET 1700000   // EE + NN self loops
#define FIN 128
#define HD 64
#define CC 10

#define CSRB 296     // 2 blocks/SM — co-resident single wave, occ 100%
#define CSRT 512

// ---- static device scratch (no dynamic allocation allowed) ----
__device__ float4 g_h[2][NN * (HD / 4)];   // two ping-pong feature buffers
__device__ float  g_inv[2][NN];            // per-node 1/||h||
__device__ int    g_deg[NN];
__device__ int    g_rowptr[NN + 1];
__device__ int    g_cursor[NN];
__device__ int    g_csrc[ET];
__device__ int    g_is64;                  // edge_index dtype flag
__device__ int    g_bsum2[CSRB];
__device__ unsigned g_gbar;                // global barrier counter (reset each call)
__device__ unsigned g_gdone;               // completion counter (reset each call)

// packed fp32x2 FMA (2x scalar FFMA throughput; exact fp32 numerics)
__device__ __forceinline__ void ffma2(float2& d, float a, float2 b) {
    float2 av = make_float2(a, a);
    unsigned long long aa = *(unsigned long long*)&av;
    unsigned long long bb = *(unsigned long long*)&b;
    unsigned long long dd = *(unsigned long long*)&d;
    asm("fma.rn.f32x2 %0, %1, %2, %0;" : "+l"(dd) : "l"(aa), "l"(bb));
    d = *(float2*)&dd;
}

__device__ __forceinline__ int clampn(int v) {
    return v < 0 ? 0 : (v >= NN ? NN - 1 : v);
}

// load a pair of edge indices (2 consecutive entries) with one 16B/8B load
__device__ __forceinline__ void edge_pair(const void* ei, long long pair_idx,
                                          int is64, int& v0, int& v1) {
    if (is64) {
        longlong2 v = ((const longlong2*)ei)[pair_idx];
        v0 = clampn((int)v.x); v1 = clampn((int)v.y);
    } else {
        int2 v = ((const int2*)ei)[pair_idx];
        v0 = clampn(v.x); v1 = clampn(v.y);
    }
}

// grid-wide barrier: all blocks arrive (counting, monotonic target = phase*nb)
__device__ __forceinline__ void gbar(unsigned phase, unsigned nb) {
    __syncthreads();
    if (threadIdx.x == 0) {
        asm volatile("red.release.gpu.global.add.u32 [%0], 1;" :: "l"(&g_gbar) : "memory");
        unsigned target = phase * nb;
        unsigned v;
        do {
            asm volatile("ld.acquire.gpu.global.u32 %0, [%1];" : "=r"(v) : "l"(&g_gbar) : "memory");
        } while (v < target);
    }
    __syncthreads();
}

// no-op kernel: ncu capture lands on the 4th launch (index 3);
// order csr,noop,noop,gemm1 puts gemm1 in the captured slot.
__global__ void noop_kernel() {}

// ---------------------------------------------------------------
// Fused CSR build: detect dtype, degree histogram, prefix scan,
// scatter. One persistent kernel, 296 blocks x 512 threads
// (2 blocks/SM co-resident — double warp count for atomic latency),
// global barriers between phases. Vectorized (2-edge) index loads.
// ---------------------------------------------------------------
__global__ void __launch_bounds__(CSRT, 2) csr_kernel(const void* __restrict__ ei) {
    const unsigned nb = gridDim.x;
    int tid = threadIdx.x, bid = blockIdx.x;
    int gi = bid * CSRT + tid;
    int gstride = nb * CSRT;

    // ---- phase A: dtype detect + deg init ----
    if (bid == 0 && tid == 0) {
        const int* p = (const int*)ei;
        int ornz = 0;
#pragma unroll
        for (int i = 0; i < 16; i++) ornz |= p[2 * i + 1];
        g_is64 = (ornz == 0) ? 1 : 0;
    }
    for (int i = gi; i < NN; i += gstride) g_deg[i] = 1;  // self loop pre-counted
    gbar(1, nb);

    int is64 = g_is64;

    // ---- phase B: degree histogram (2 edges per thread, 16B loads) ----
    for (int p = gi; p < EE / 2; p += gstride) {
        int d0, d1;
        edge_pair(ei, (long long)(EE / 2) + p, is64, d0, d1);
        atomicAdd(&g_deg[d0], 1);
        atomicAdd(&g_deg[d1], 1);
    }
    gbar(2, nb);

    // ---- phase C: prefix scan ----
    const int chunk = (NN + CSRB - 1) / CSRB;   // 338
    int lo = bid * chunk;
    int hi = lo + chunk; if (hi > NN) hi = NN;
    if (lo > NN) lo = NN;
    __shared__ int sh[CSRT];
    __shared__ int sb[CSRT];
    int dval = (lo + tid < hi) ? g_deg[lo + tid] : 0;
    sh[tid] = dval;
    __syncthreads();
    for (int off = 1; off < CSRT; off <<= 1) {
        int v = (tid >= off) ? sh[tid - off] : 0;
        __syncthreads();
        sh[tid] += v;
        __syncthreads();
    }
    if (tid == 0) g_bsum2[bid] = sh[CSRT - 1];
    gbar(3, nb);

    sb[tid] = (tid < (int)nb) ? g_bsum2[tid] : 0;
    __syncthreads();
    for (int off = 1; off < CSRT; off <<= 1) {
        int v = (tid >= off) ? sb[tid - off] : 0;
        __syncthreads();
        sb[tid] += v;
        __syncthreads();
    }
    int boff = (bid == 0) ? 0 : sb[bid - 1];
    if (lo + tid < hi) {
        int excl = boff + sh[tid] - dval;
        g_rowptr[lo + tid] = excl;
        g_cursor[lo + tid] = excl;
    }
    if (bid == (int)nb - 1 && tid == 0) g_rowptr[NN] = ET;
    gbar(4, nb);

    // ---- phase D: scatter (2 edges per thread, 16B loads) ----
    for (int p = gi; p < EE / 2; p += gstride) {
        int s0, s1, d0, d1;
        edge_pair(ei, (long long)p, is64, s0, s1);                 // src pair
        edge_pair(ei, (long long)(EE / 2) + p, is64, d0, d1);      // dst pair
        int pos0 = atomicAdd(&g_cursor[d0], 1);
        if (pos0 >= 0 && pos0 < ET) g_csrc[pos0] = s0;
        int pos1 = atomicAdd(&g_cursor[d1], 1);
        if (pos1 >= 0 && pos1 < ET) g_csrc[pos1] = s1;
    }
    // self loops
    for (int i = EE + gi; i < ET; i += gstride) {
        int sd = i - EE;
        int pos = atomicAdd(&g_cursor[sd], 1);
        if (pos >= 0 && pos < ET) g_csrc[pos] = sd;
    }

    // ---- reset barrier counters for the next graph replay ----
    __syncthreads();
    if (tid == 0) {
        unsigned done = atomicAdd(&g_gdone, 1);
        if (done == nb - 1) {           // last block: everyone else is finished
            atomicExch(&g_gbar, 0u);
            atomicExch(&g_gdone, 0u);
        }
    }
}

// ---------------------------------------------------------------
// GEMM1: h0 = relu(x @ W1 + b1) + inv-norm epilogue.
// 32 nodes/block, 128 threads; thread = (node-group of 4, col quad).
// smem: 32KB W + 16KB x-tile = 48KB static.
// ---------------------------------------------------------------
#define G1B 32
__global__ void gemm1_kernel(const float* __restrict__ x,
                             const float* __restrict__ W1,
                             const float* __restrict__ b1) {
    __shared__ float ws[FIN * HD];     // 32 KB
    __shared__ float xs[G1B * FIN];    // 16 KB
    int tid = threadIdx.x;
    for (int i = tid; i < FIN * HD; i += 128) ws[i] = W1[i];
    int base = blockIdx.x * G1B;
    {
        float4* xsv = (float4*)xs;
        const float4* xv = (const float4*)x;
        for (int i = tid; i < G1B * (FIN / 4); i += 128) {
            int row = i >> 5;            // FIN/4 = 32
            int col = i & 31;
            int gr = base + row; if (gr >= NN) gr = NN - 1;
            xsv[i] = xv[(size_t)gr * 32 + col];
        }
    }
    __syncthreads();

    int ng = tid >> 4;     // node group 0..7 (4 nodes each)
    int cq = tid & 15;     // column quad 0..15
    int c  = cq * 4;

    float2 a01[4], a23[4];
#pragma unroll
    for (int j = 0; j < 4; j++) { a01[j] = make_float2(0.f, 0.f); a23[j] = make_float2(0.f, 0.f); }

    for (int k4 = 0; k4 < 32; k4++) {
        float4 xv[4];
#pragma unroll
        for (int j = 0; j < 4; j++)
            xv[j] = *(const float4*)&xs[(ng * 4 + j) * FIN + k4 * 4];
#pragma unroll
        for (int kk = 0; kk < 4; kk++) {
            float4 w = *(const float4*)&ws[(k4 * 4 + kk) * HD + c];
            float2 w01 = make_float2(w.x, w.y);
            float2 w23 = make_float2(w.z, w.w);
#pragma unroll
            for (int j = 0; j < 4; j++) {
                float xk = (kk == 0) ? xv[j].x : (kk == 1) ? xv[j].y : (kk == 2) ? xv[j].z : xv[j].w;
                ffma2(a01[j], xk, w01);
                ffma2(a23[j], xk, w23);
            }
        }
    }

    float4 bb = *(const float4*)&b1[c];
#pragma unroll
    for (int j = 0; j < 4; j++) {
        float4 o;
        o.x = fmaxf(a01[j].x + bb.x, 0.f);
        o.y = fmaxf(a01[j].y + bb.y, 0.f);
        o.z = fmaxf(a23[j].x + bb.z, 0.f);
        o.w = fmaxf(a23[j].y + bb.w, 0.f);
        float sq = o.x * o.x + o.y * o.y + o.z * o.z + o.w * o.w;
        sq += __shfl_xor_sync(0xFFFFFFFFu, sq, 8);
        sq += __shfl_xor_sync(0xFFFFFFFFu, sq, 4);
        sq += __shfl_xor_sync(0xFFFFFFFFu, sq, 2);
        sq += __shfl_xor_sync(0xFFFFFFFFu, sq, 1);
        int node = base + ng * 4 + j;
        if (node < NN) {
            g_h[0][(size_t)node * 16 + cq] = o;
            if (cq == 0) g_inv[0][node] = rsqrtf(fmaxf(sq, 1e-24f));
        }
    }
}

// ---------------------------------------------------------------
// Fused AGNN layer (R12 best config): warp per dst node, 4 edges in
// flight (8 lanes/edge), contiguous 128B gathers, csrc prefetch,
// unroll 2. __launch_bounds__(256, 5): 48 regs spill-free, 40 warps/SM.
// ---------------------------------------------------------------
__global__ void __launch_bounds__(256, 5) agnn_kernel(int cur) {
    const float4* __restrict__ h   = g_h[cur];
    const float*  __restrict__ inv = g_inv[cur];
    float4* hout   = g_h[cur ^ 1];
    float*  invout = g_inv[cur ^ 1];

    int gw = (blockIdx.x * blockDim.x + threadIdx.x) >> 5;
    if (gw >= NN) return;
    int lane = threadIdx.x & 31;
    int grp  = lane >> 3;       // edge slot within iteration (0..3)
    int fl   = lane & 7;        // float4 index: owns quads fl and fl+8

    float4 hd0 = h[(size_t)gw * 16 + fl];
    float4 hd1 = h[(size_t)gw * 16 + fl + 8];
    float  invd = inv[gw];
    int beg = g_rowptr[gw];
    int end = g_rowptr[gw + 1];

    float4 acc0 = make_float4(0.f, 0.f, 0.f, 0.f);
    float4 acc1 = make_float4(0.f, 0.f, 0.f, 0.f);
    float denom = 0.f;

    int iters = (end - beg + 3) >> 2;
    int e0 = beg + grp;
    bool v_next = e0 < end;
    int s_next = v_next ? g_csrc[e0] : gw;

#pragma unroll 2
    for (int it = 0; it < iters; it++) {
        int s = s_next;
        bool valid = v_next;
        int en = beg + 4 * (it + 1) + grp;
        v_next = en < end;
        s_next = v_next ? g_csrc[en] : gw;

        float4 a = h[(size_t)s * 16 + fl];       // line 0 of src row
        float4 b = h[(size_t)s * 16 + fl + 8];   // line 1 of src row
        float invs = inv[s];
        float p = a.x * hd0.x + a.y * hd0.y + a.z * hd0.z + a.w * hd0.w
                + b.x * hd1.x + b.y * hd1.y + b.z * hd1.z + b.w * hd1.w;
        p += __shfl_xor_sync(0xFFFFFFFFu, p, 4);
        p += __shfl_xor_sync(0xFFFFFFFFu, p, 2);
        p += __shfl_xor_sync(0xFFFFFFFFu, p, 1);
        float w = valid ? __expf(p * invd * invs) : 0.f;
        denom += w;
        acc0.x += w * a.x; acc0.y += w * a.y; acc0.z += w * a.z; acc0.w += w * a.w;
        acc1.x += w * b.x; acc1.y += w * b.y; acc1.z += w * b.z; acc1.w += w * b.w;
    }

#pragma unroll
    for (int off = 8; off <= 16; off <<= 1) {
        acc0.x += __shfl_xor_sync(0xFFFFFFFFu, acc0.x, off);
        acc0.y += __shfl_xor_sync(0xFFFFFFFFu, acc0.y, off);
        acc0.z += __shfl_xor_sync(0xFFFFFFFFu, acc0.z, off);
        acc0.w += __shfl_xor_sync(0xFFFFFFFFu, acc0.w, off);
        acc1.x += __shfl_xor_sync(0xFFFFFFFFu, acc1.x, off);
        acc1.y += __shfl_xor_sync(0xFFFFFFFFu, acc1.y, off);
        acc1.z += __shfl_xor_sync(0xFFFFFFFFu, acc1.z, off);
        acc1.w += __shfl_xor_sync(0xFFFFFFFFu, acc1.w, off);
        denom  += __shfl_xor_sync(0xFFFFFFFFu, denom, off);
    }

    float r = 1.f / fmaxf(denom, 1e-16f);
    float4 o0 = make_float4(acc0.x * r, acc0.y * r, acc0.z * r, acc0.w * r);
    float4 o1 = make_float4(acc1.x * r, acc1.y * r, acc1.z * r, acc1.w * r);

    float sq = o0.x * o0.x + o0.y * o0.y + o0.z * o0.z + o0.w * o0.w
             + o1.x * o1.x + o1.y * o1.y + o1.z * o1.z + o1.w * o1.w;
    sq += __shfl_xor_sync(0xFFFFFFFFu, sq, 4);
    sq += __shfl_xor_sync(0xFFFFFFFFu, sq, 2);
    sq += __shfl_xor_sync(0xFFFFFFFFu, sq, 1);

    if (grp == 0) {
        hout[(size_t)gw * 16 + fl]     = o0;
        hout[(size_t)gw * 16 + fl + 8] = o1;
        if (fl == 0) invout[gw] = rsqrtf(fmaxf(sq, 1e-24f));
    }
}

// ---------------------------------------------------------------
// GEMM2 + log_softmax: thread per node
// ---------------------------------------------------------------
__global__ void gemm2_kernel(const float* __restrict__ W2,
                             const float* __restrict__ b2,
                             float* __restrict__ out, int cur) {
    __shared__ float w2s[HD * CC];
    __shared__ float b2s[CC];
    for (int i = threadIdx.x; i < HD * CC; i += blockDim.x) w2s[i] = W2[i];
    if (threadIdx.x < CC) b2s[threadIdx.x] = b2[threadIdx.x];
    __syncthreads();

    int node = blockIdx.x * blockDim.x + threadIdx.x;
    if (node >= NN) return;

    const float4* hp = (const float4*)g_h[cur] + (size_t)node * 16;
    float acc[CC];
#pragma unroll
    for (int j = 0; j < CC; j++) acc[j] = b2s[j];
#pragma unroll
    for (int k4 = 0; k4 < 16; k4++) {
        float4 hv = hp[k4];
#pragma unroll
        for (int j = 0; j < CC; j++) {
            acc[j] += hv.x * w2s[(4 * k4 + 0) * CC + j]
                    + hv.y * w2s[(4 * k4 + 1) * CC + j]
                    + hv.z * w2s[(4 * k4 + 2) * CC + j]
                    + hv.w * w2s[(4 * k4 + 3) * CC + j];
        }
    }
    float m = acc[0];
#pragma unroll
    for (int j = 1; j < CC; j++) m = fmaxf(m, acc[j]);
    float ssum = 0.f;
#pragma unroll
    for (int j = 0; j < CC; j++) ssum += __expf(acc[j] - m);
    float lse = m + logf(ssum);
#pragma unroll
    for (int j = 0; j < CC; j++) out[(size_t)node * CC + j] = acc[j] - lse;
}

// ---------------------------------------------------------------
extern "C" void kernel_launch(void* const* d_in, const int* in_sizes, int n_in,
                              void* d_out, int out_size) {
    const float* x = nullptr; const void* ei = nullptr;
    const float* W1 = nullptr; const float* b1 = nullptr;
    const float* W2 = nullptr; const float* b2 = nullptr;
    for (int i = 0; i < n_in; i++) {
        switch (in_sizes[i]) {
            case NN * FIN:   x  = (const float*)d_in[i]; break;
            case 2 * EE:     ei = d_in[i]; break;
            case FIN * HD:   W1 = (const float*)d_in[i]; break;
            case HD:         b1 = (const float*)d_in[i]; break;
            case HD * CC:    W2 = (const float*)d_in[i]; break;
            case CC:         b2 = (const float*)d_in[i]; break;
            default: break;
        }
    }
    float* out = (float*)d_out;

    // capture slot = 4th launch: csr, noop, noop, gemm1 -> gemm1 profiled
    csr_kernel<<<CSRB, CSRT>>>(ei);
    noop_kernel<<<1, 32>>>();
    noop_kernel<<<1, 32>>>();
    gemm1_kernel<<<(NN + G1B - 1) / G1B, 128>>>(x, W1, b1);   // launch 4 <- profiled
    for (int l = 0; l < 4; l++)
        agnn_kernel<<<(NN + 7) / 8, 256>>>(l & 1);
    gemm2_kernel<<<(NN + 255) / 256, 256>>>(W2, b2, out, 0);
}

// round 17
// speedup vs baseline: 1.0619x; 1.0619x over previous
#include <cuda_runtime.h>

#define NN 100000
#define EE 1600000
#define ET 1700000   // EE + NN self loops
#define FIN 128
#define HD 64
#define CC 10

#define CSRB 296     // 2 blocks/SM — co-resident single wave
#define CSRT 512

// ---- static device scratch (no dynamic allocation allowed) ----
__device__ float4 g_h[2][NN * (HD / 4)];   // two ping-pong feature buffers
__device__ float  g_inv[2][NN];            // per-node 1/||h||
__device__ int    g_deg[NN];
__device__ int    g_rowptr[NN + 1];
__device__ int    g_cursor[NN];
__device__ int    g_csrc[ET];
__device__ int    g_is64;                  // edge_index dtype flag
__device__ int    g_bsum2[CSRB];
__device__ unsigned g_gbar;                // global barrier counter (reset each call)
__device__ unsigned g_gdone;               // completion counter (reset each call)

// packed fp32x2 FMA (2x scalar FFMA throughput; exact fp32 numerics)
__device__ __forceinline__ void ffma2(float2& d, float a, float2 b) {
    float2 av = make_float2(a, a);
    unsigned long long aa = *(unsigned long long*)&av;
    unsigned long long bb = *(unsigned long long*)&b;
    unsigned long long dd = *(unsigned long long*)&d;
    asm("fma.rn.f32x2 %0, %1, %2, %0;" : "+l"(dd) : "l"(aa), "l"(bb));
    d = *(float2*)&dd;
}

__device__ __forceinline__ int clampn(int v) {
    return v < 0 ? 0 : (v >= NN ? NN - 1 : v);
}

// load a pair of edge indices (2 consecutive entries) with one 16B/8B load
__device__ __forceinline__ void edge_pair(const void* ei, long long pair_idx,
                                          int is64, int& v0, int& v1) {
    if (is64) {
        longlong2 v = ((const longlong2*)ei)[pair_idx];
        v0 = clampn((int)v.x); v1 = clampn((int)v.y);
    } else {
        int2 v = ((const int2*)ei)[pair_idx];
        v0 = clampn(v.x); v1 = clampn(v.y);
    }
}

// grid-wide barrier: all blocks arrive (counting, monotonic target = phase*nb)
__device__ __forceinline__ void gbar(unsigned phase, unsigned nb) {
    __syncthreads();
    if (threadIdx.x == 0) {
        asm volatile("red.release.gpu.global.add.u32 [%0], 1;" :: "l"(&g_gbar) : "memory");
        unsigned target = phase * nb;
        unsigned v;
        do {
            asm volatile("ld.acquire.gpu.global.u32 %0, [%1];" : "=r"(v) : "l"(&g_gbar) : "memory");
        } while (v < target);
    }
    __syncthreads();
}

// no-op kernel: ncu capture lands on the 4th launch (index 3)
__global__ void noop_kernel() {}

// ---------------------------------------------------------------
// Fused CSR build: one persistent kernel, 296 blocks x 512 threads,
// global barriers between phases, vectorized (2-edge) index loads.
// ---------------------------------------------------------------
__global__ void __launch_bounds__(CSRT, 2) csr_kernel(const void* __restrict__ ei) {
    const unsigned nb = gridDim.x;
    int tid = threadIdx.x, bid = blockIdx.x;
    int gi = bid * CSRT + tid;
    int gstride = nb * CSRT;

    // ---- phase A: dtype detect + deg init ----
    if (bid == 0 && tid == 0) {
        const int* p = (const int*)ei;
        int ornz = 0;
#pragma unroll
        for (int i = 0; i < 16; i++) ornz |= p[2 * i + 1];
        g_is64 = (ornz == 0) ? 1 : 0;
    }
    for (int i = gi; i < NN; i += gstride) g_deg[i] = 1;  // self loop pre-counted
    gbar(1, nb);

    int is64 = g_is64;

    // ---- phase B: degree histogram (2 edges per thread) ----
    for (int p = gi; p < EE / 2; p += gstride) {
        int d0, d1;
        edge_pair(ei, (long long)(EE / 2) + p, is64, d0, d1);
        atomicAdd(&g_deg[d0], 1);
        atomicAdd(&g_deg[d1], 1);
    }
    gbar(2, nb);

    // ---- phase C: prefix scan ----
    const int chunk = (NN + CSRB - 1) / CSRB;   // 338
    int lo = bid * chunk;
    int hi = lo + chunk; if (hi > NN) hi = NN;
    if (lo > NN) lo = NN;
    __shared__ int sh[CSRT];
    __shared__ int sb[CSRT];
    int dval = (lo + tid < hi) ? g_deg[lo + tid] : 0;
    sh[tid] = dval;
    __syncthreads();
    for (int off = 1; off < CSRT; off <<= 1) {
        int v = (tid >= off) ? sh[tid - off] : 0;
        __syncthreads();
        sh[tid] += v;
        __syncthreads();
    }
    if (tid == 0) g_bsum2[bid] = sh[CSRT - 1];
    gbar(3, nb);

    sb[tid] = (tid < (int)nb) ? g_bsum2[tid] : 0;
    __syncthreads();
    for (int off = 1; off < CSRT; off <<= 1) {
        int v = (tid >= off) ? sb[tid - off] : 0;
        __syncthreads();
        sb[tid] += v;
        __syncthreads();
    }
    int boff = (bid == 0) ? 0 : sb[bid - 1];
    if (lo + tid < hi) {
        int excl = boff + sh[tid] - dval;
        g_rowptr[lo + tid] = excl;
        g_cursor[lo + tid] = excl;
    }
    if (bid == (int)nb - 1 && tid == 0) g_rowptr[NN] = ET;
    gbar(4, nb);

    // ---- phase D: scatter (2 edges per thread) ----
    for (int p = gi; p < EE / 2; p += gstride) {
        int s0, s1, d0, d1;
        edge_pair(ei, (long long)p, is64, s0, s1);                 // src pair
        edge_pair(ei, (long long)(EE / 2) + p, is64, d0, d1);      // dst pair
        int pos0 = atomicAdd(&g_cursor[d0], 1);
        if (pos0 >= 0 && pos0 < ET) g_csrc[pos0] = s0;
        int pos1 = atomicAdd(&g_cursor[d1], 1);
        if (pos1 >= 0 && pos1 < ET) g_csrc[pos1] = s1;
    }
    // self loops
    for (int i = EE + gi; i < ET; i += gstride) {
        int sd = i - EE;
        int pos = atomicAdd(&g_cursor[sd], 1);
        if (pos >= 0 && pos < ET) g_csrc[pos] = sd;
    }

    // ---- reset barrier counters for the next graph replay ----
    __syncthreads();
    if (tid == 0) {
        unsigned done = atomicAdd(&g_gdone, 1);
        if (done == nb - 1) {
            atomicExch(&g_gbar, 0u);
            atomicExch(&g_gdone, 0u);
        }
    }
}

// ---------------------------------------------------------------
// GEMM1: h0 = relu(x @ W1 + b1) + inv-norm epilogue.
// 64 nodes/block, 256 threads; thread = (node-group of 4, col quad).
// smem: W only (32KB) — x read via warp-broadcast global loads
// (all 16 cq threads of a group hit the same address -> 1 line).
// Occupancy: 7 blocks/SM (smem-limited) = 1792 thr = 87%
// vs old 24% (48KB smem @ 128 thr).
// ---------------------------------------------------------------
#define G1B 64
__global__ void __launch_bounds__(256) gemm1_kernel(const float* __restrict__ x,
                             const float* __restrict__ W1,
                             const float* __restrict__ b1) {
    __shared__ float ws[FIN * HD];     // 32 KB
    int tid = threadIdx.x;
    for (int i = tid; i < FIN * HD; i += 256) ws[i] = W1[i];
    __syncthreads();

    int ng = tid >> 4;     // node group 0..15 (4 nodes each)
    int cq = tid & 15;     // column quad 0..15
    int c  = cq * 4;
    int base = blockIdx.x * G1B + ng * 4;

    // clamped row pointers (tail block safety; duplicates are harmless)
    const float4* xr[4];
#pragma unroll
    for (int j = 0; j < 4; j++)
        xr[j] = (const float4*)x + (size_t)clampn(base + j) * 32;

    float2 a01[4], a23[4];
#pragma unroll
    for (int j = 0; j < 4; j++) { a01[j] = make_float2(0.f, 0.f); a23[j] = make_float2(0.f, 0.f); }

    for (int k4 = 0; k4 < 32; k4++) {
        float4 xv[4];
#pragma unroll
        for (int j = 0; j < 4; j++)
            xv[j] = xr[j][k4];          // broadcast across the 16 cq threads
#pragma unroll
        for (int kk = 0; kk < 4; kk++) {
            float4 w = *(const float4*)&ws[(k4 * 4 + kk) * HD + c];
            float2 w01 = make_float2(w.x, w.y);
            float2 w23 = make_float2(w.z, w.w);
#pragma unroll
            for (int j = 0; j < 4; j++) {
                float xk = (kk == 0) ? xv[j].x : (kk == 1) ? xv[j].y : (kk == 2) ? xv[j].z : xv[j].w;
                ffma2(a01[j], xk, w01);
                ffma2(a23[j], xk, w23);
            }
        }
    }

    float4 bb = *(const float4*)&b1[c];
#pragma unroll
    for (int j = 0; j < 4; j++) {
        float4 o;
        o.x = fmaxf(a01[j].x + bb.x, 0.f);
        o.y = fmaxf(a01[j].y + bb.y, 0.f);
        o.z = fmaxf(a23[j].x + bb.z, 0.f);
        o.w = fmaxf(a23[j].y + bb.w, 0.f);
        float sq = o.x * o.x + o.y * o.y + o.z * o.z + o.w * o.w;
        sq += __shfl_xor_sync(0xFFFFFFFFu, sq, 8);
        sq += __shfl_xor_sync(0xFFFFFFFFu, sq, 4);
        sq += __shfl_xor_sync(0xFFFFFFFFu, sq, 2);
        sq += __shfl_xor_sync(0xFFFFFFFFu, sq, 1);
        int node = base + j;
        if (node < NN) {
            g_h[0][(size_t)node * 16 + cq] = o;
            if (cq == 0) g_inv[0][node] = rsqrtf(fmaxf(sq, 1e-24f));
        }
    }
}

// ---------------------------------------------------------------
// Fused AGNN layer (R12 best config): warp per dst node, 4 edges in
// flight (8 lanes/edge), contiguous 128B gathers, csrc prefetch,
// unroll 2. __launch_bounds__(256, 5): 48 regs spill-free, 40 warps/SM.
// ---------------------------------------------------------------
__global__ void __launch_bounds__(256, 5) agnn_kernel(int cur) {
    const float4* __restrict__ h   = g_h[cur];
    const float*  __restrict__ inv = g_inv[cur];
    float4* hout   = g_h[cur ^ 1];
    float*  invout = g_inv[cur ^ 1];

    int gw = (blockIdx.x * blockDim.x + threadIdx.x) >> 5;
    if (gw >= NN) return;
    int lane = threadIdx.x & 31;
    int grp  = lane >> 3;       // edge slot within iteration (0..3)
    int fl   = lane & 7;        // float4 index: owns quads fl and fl+8

    float4 hd0 = h[(size_t)gw * 16 + fl];
    float4 hd1 = h[(size_t)gw * 16 + fl + 8];
    float  invd = inv[gw];
    int beg = g_rowptr[gw];
    int end = g_rowptr[gw + 1];

    float4 acc0 = make_float4(0.f, 0.f, 0.f, 0.f);
    float4 acc1 = make_float4(0.f, 0.f, 0.f, 0.f);
    float denom = 0.f;

    int iters = (end - beg + 3) >> 2;
    int e0 = beg + grp;
    bool v_next = e0 < end;
    int s_next = v_next ? g_csrc[e0] : gw;

#pragma unroll 2
    for (int it = 0; it < iters; it++) {
        int s = s_next;
        bool valid = v_next;
        int en = beg + 4 * (it + 1) + grp;
        v_next = en < end;
        s_next = v_next ? g_csrc[en] : gw;

        float4 a = h[(size_t)s * 16 + fl];       // line 0 of src row
        float4 b = h[(size_t)s * 16 + fl + 8];   // line 1 of src row
        float invs = inv[s];
        float p = a.x * hd0.x + a.y * hd0.y + a.z * hd0.z + a.w * hd0.w
                + b.x * hd1.x + b.y * hd1.y + b.z * hd1.z + b.w * hd1.w;
        p += __shfl_xor_sync(0xFFFFFFFFu, p, 4);
        p += __shfl_xor_sync(0xFFFFFFFFu, p, 2);
        p += __shfl_xor_sync(0xFFFFFFFFu, p, 1);
        float w = valid ? __expf(p * invd * invs) : 0.f;
        denom += w;
        acc0.x += w * a.x; acc0.y += w * a.y; acc0.z += w * a.z; acc0.w += w * a.w;
        acc1.x += w * b.x; acc1.y += w * b.y; acc1.z += w * b.z; acc1.w += w * b.w;
    }

#pragma unroll
    for (int off = 8; off <= 16; off <<= 1) {
        acc0.x += __shfl_xor_sync(0xFFFFFFFFu, acc0.x, off);
        acc0.y += __shfl_xor_sync(0xFFFFFFFFu, acc0.y, off);
        acc0.z += __shfl_xor_sync(0xFFFFFFFFu, acc0.z, off);
        acc0.w += __shfl_xor_sync(0xFFFFFFFFu, acc0.w, off);
        acc1.x += __shfl_xor_sync(0xFFFFFFFFu, acc1.x, off);
        acc1.y += __shfl_xor_sync(0xFFFFFFFFu, acc1.y, off);
        acc1.z += __shfl_xor_sync(0xFFFFFFFFu, acc1.z, off);
        acc1.w += __shfl_xor_sync(0xFFFFFFFFu, acc1.w, off);
        denom  += __shfl_xor_sync(0xFFFFFFFFu, denom, off);
    }

    float r = 1.f / fmaxf(denom, 1e-16f);
    float4 o0 = make_float4(acc0.x * r, acc0.y * r, acc0.z * r, acc0.w * r);
    float4 o1 = make_float4(acc1.x * r, acc1.y * r, acc1.z * r, acc1.w * r);

    float sq = o0.x * o0.x + o0.y * o0.y + o0.z * o0.z + o0.w * o0.w
             + o1.x * o1.x + o1.y * o1.y + o1.z * o1.z + o1.w * o1.w;
    sq += __shfl_xor_sync(0xFFFFFFFFu, sq, 4);
    sq += __shfl_xor_sync(0xFFFFFFFFu, sq, 2);
    sq += __shfl_xor_sync(0xFFFFFFFFu, sq, 1);

    if (grp == 0) {
        hout[(size_t)gw * 16 + fl]     = o0;
        hout[(size_t)gw * 16 + fl + 8] = o1;
        if (fl == 0) invout[gw] = rsqrtf(fmaxf(sq, 1e-24f));
    }
}

// ---------------------------------------------------------------
// GEMM2 + log_softmax: thread per node
// ---------------------------------------------------------------
__global__ void gemm2_kernel(const float* __restrict__ W2,
                             const float* __restrict__ b2,
                             float* __restrict__ out, int cur) {
    __shared__ float w2s[HD * CC];
    __shared__ float b2s[CC];
    for (int i = threadIdx.x; i < HD * CC; i += blockDim.x) w2s[i] = W2[i];
    if (threadIdx.x < CC) b2s[threadIdx.x] = b2[threadIdx.x];
    __syncthreads();

    int node = blockIdx.x * blockDim.x + threadIdx.x;
    if (node >= NN) return;

    const float4* hp = (const float4*)g_h[cur] + (size_t)node * 16;
    float acc[CC];
#pragma unroll
    for (int j = 0; j < CC; j++) acc[j] = b2s[j];
#pragma unroll
    for (int k4 = 0; k4 < 16; k4++) {
        float4 hv = hp[k4];
#pragma unroll
        for (int j = 0; j < CC; j++) {
            acc[j] += hv.x * w2s[(4 * k4 + 0) * CC + j]
                    + hv.y * w2s[(4 * k4 + 1) * CC + j]
                    + hv.z * w2s[(4 * k4 + 2) * CC + j]
                    + hv.w * w2s[(4 * k4 + 3) * CC + j];
        }
    }
    float m = acc[0];
#pragma unroll
    for (int j = 1; j < CC; j++) m = fmaxf(m, acc[j]);
    float ssum = 0.f;
#pragma unroll
    for (int j = 0; j < CC; j++) ssum += __expf(acc[j] - m);
    float lse = m + logf(ssum);
#pragma unroll
    for (int j = 0; j < CC; j++) out[(size_t)node * CC + j] = acc[j] - lse;
}

// ---------------------------------------------------------------
extern "C" void kernel_launch(void* const* d_in, const int* in_sizes, int n_in,
                              void* d_out, int out_size) {
    const float* x = nullptr; const void* ei = nullptr;
    const float* W1 = nullptr; const float* b1 = nullptr;
    const float* W2 = nullptr; const float* b2 = nullptr;
    for (int i = 0; i < n_in; i++) {
        switch (in_sizes[i]) {
            case NN * FIN:   x  = (const float*)d_in[i]; break;
            case 2 * EE:     ei = d_in[i]; break;
            case FIN * HD:   W1 = (const float*)d_in[i]; break;
            case HD:         b1 = (const float*)d_in[i]; break;
            case HD * CC:    W2 = (const float*)d_in[i]; break;
            case CC:         b2 = (const float*)d_in[i]; break;
            default: break;
        }
    }
    float* out = (float*)d_out;

    // capture slot = 4th launch: csr, noop, noop, gemm1 -> gemm1 profiled
    csr_kernel<<<CSRB, CSRT>>>(ei);
    noop_kernel<<<1, 32>>>();
    noop_kernel<<<1, 32>>>();
    gemm1_kernel<<<(NN + G1B - 1) / G1B, 256>>>(x, W1, b1);   // launch 4 <- profiled
    for (int l = 0; l < 4; l++)
        agnn_kernel<<<(NN + 7) / 8, 256>>>(l & 1);
    gemm2_kernel<<<(NN + 255) / 256, 256>>>(W2, b2, out, 0);
}